// round 13
// baseline (speedup 1.0000x reference)
#include <cuda_runtime.h>
#include <cuda_fp16.h>
#include <cstdint>

#define Nn 16384
#define Ee 262144
#define Rr 9
#define DIN 384
#define DH 768
#define NC 5
#define KREL (Rr * DIN)     // 3456
#define NMP (2 * DH)        // 1536

// ---------------- scratch (device globals) --------------------------------
__device__ __align__(256) __half g_xh[(size_t)Nn * DIN];
__device__ __align__(256) float g_norm[Ee];
__device__ __align__(256) __half g_Shi[(size_t)Nn * KREL];
__device__ __align__(256) float g_C[Nn * Rr];
__device__ __align__(256) __half g_Brel[(size_t)DH * KREL];
__device__ __align__(256) __half g_x1[(size_t)Nn * DH];
__device__ __align__(256) __half g_Bmp[(size_t)NMP * DH];
__device__ __align__(256) __half g_hm[(size_t)Nn * DH];
__device__ __align__(256) __half g_self[(size_t)Nn * DH];
__device__ float g_pooled[DH];
// CSR
__device__ int g_cnt[Nn];
__device__ int g_rowptr[Nn + 1];
__device__ int g_woff[Nn];
__device__ int g_eids[Ee];

// ---------------- PTX helpers ---------------------------------------------
__device__ __forceinline__ uint32_t smem_u32(const void* p) {
    uint32_t a;
    asm("{ .reg .u64 t; cvta.to.shared.u64 t, %1; cvt.u32.u64 %0, t; }" : "=r"(a) : "l"(p));
    return a;
}

#define CP_ASYNC16(sa, gp) \
    asm volatile("cp.async.cg.shared.global [%0], [%1], 16;" :: "r"(sa), "l"(gp))
#define CP_COMMIT() asm volatile("cp.async.commit_group;" ::: "memory")
#define CP_WAIT1()  asm volatile("cp.async.wait_group 1;" ::: "memory")
#define CP_WAIT0()  asm volatile("cp.async.wait_group 0;" ::: "memory")

#define LDMX4(r, a) \
    asm volatile("ldmatrix.sync.aligned.m8n8.x4.shared.b16 {%0,%1,%2,%3}, [%4];" \
        : "=r"((r)[0]), "=r"((r)[1]), "=r"((r)[2]), "=r"((r)[3]) : "r"(a))

#define MMAF16(c, a, b0, b1) \
    asm volatile("mma.sync.aligned.m16n8k16.row.col.f32.f16.f16.f32 " \
        "{%0,%1,%2,%3}, {%4,%5,%6,%7}, {%8,%9}, {%0,%1,%2,%3};" \
        : "+f"((c)[0]), "+f"((c)[1]), "+f"((c)[2]), "+f"((c)[3]) \
        : "r"((a)[0]), "r"((a)[1]), "r"((a)[2]), "r"((a)[3]), "r"(b0), "r"(b1))

// ---------------- small zero + CSR build ----------------------------------
__global__ void zero_small_kernel() {
    int i = blockIdx.x * blockDim.x + threadIdx.x;
    if (i < Nn) g_cnt[i] = 0;
    if (i < DH) g_pooled[i] = 0.f;
}

__global__ void csr_count_kernel(const int* __restrict__ ei) {
    int e = blockIdx.x * blockDim.x + threadIdx.x;
    if (e < Ee) atomicAdd(&g_cnt[__ldg(ei + Ee + e)], 1);
}

__global__ void csr_scan_kernel() {
    __shared__ int ssum[256];
    int t = threadIdx.x;
    int base = t * 64;
    int s = 0;
    for (int i = 0; i < 64; i++) s += g_cnt[base + i];
    ssum[t] = s;
    __syncthreads();
    for (int off = 1; off < 256; off <<= 1) {
        int u = (t >= off) ? ssum[t - off] : 0;
        __syncthreads();
        ssum[t] += u;
        __syncthreads();
    }
    int run = (t == 0) ? 0 : ssum[t - 1];
    for (int i = 0; i < 64; i++) {
        int c = g_cnt[base + i];
        g_rowptr[base + i] = run;
        g_woff[base + i] = run;
        run += c;
    }
    if (t == 255) g_rowptr[Nn] = run;
}

__global__ void csr_fill_kernel(const int* __restrict__ ei) {
    int e = blockIdx.x * blockDim.x + threadIdx.x;
    if (e >= Ee) return;
    int pos = atomicAdd(&g_woff[__ldg(ei + Ee + e)], 1);
    g_eids[pos] = e;
}

// ---------------- converts -------------------------------------------------
__global__ void conv_x_kernel(const float* __restrict__ x) {
    int i = blockIdx.x * blockDim.x + threadIdx.x;     // handles 4
    if (i >= Nn * DIN / 4) return;
    float4 v = reinterpret_cast<const float4*>(x)[i];
    __half2 a = __floats2half2_rn(v.x, v.y);
    __half2 b = __floats2half2_rn(v.z, v.w);
    reinterpret_cast<__half2*>(g_xh)[2 * i]     = a;
    reinterpret_cast<__half2*>(g_xh)[2 * i + 1] = b;
}

__global__ void wconv_rel_kernel(const float* __restrict__ relW) {
    int idx = blockIdx.x * blockDim.x + threadIdx.x;
    if (idx >= Rr * DH * DIN) return;
    int k = idx % DIN;
    int h = (idx / DIN) % DH;
    int r = idx / (DIN * DH);
    g_Brel[(size_t)h * KREL + r * DIN + k] = __float2half_rn(relW[idx]);
}

__global__ void wconv_mp_kernel(const float* __restrict__ mplW, const float* __restrict__ mpsW) {
    int idx = blockIdx.x * blockDim.x + threadIdx.x;
    if (idx >= NMP * DH) return;
    int k = idx % DH;
    int n = idx / DH;
    float v = (n < DH) ? mplW[(size_t)n * DH + k] : mpsW[(size_t)(n - DH) * DH + k];
    g_Bmp[idx] = __float2half_rn(v);
}

// ---------------- pass A: per-edge dot (SDDMM), warp per edge -------------
__global__ __launch_bounds__(256) void norm_kernel(
    const int* __restrict__ ei, const int* __restrict__ et,
    const float* __restrict__ normc)
{
    int e = (blockIdx.x * 256 + threadIdx.x) >> 5;
    if (e >= Ee) return;
    int lane = threadIdx.x & 31;
    int src = __ldg(ei + e), dst = __ldg(ei + Ee + e);
    const __half* ps = g_xh + (size_t)src * DIN;
    const __half* pd = g_xh + (size_t)dst * DIN;
    float dot = 0.f;
    #pragma unroll
    for (int i = 0; i < 12; i++) {
        float a = __half2float(__ldg(ps + lane + 32 * i));
        float b = __half2float(__ldg(pd + lane + 32 * i));
        dot = fmaf(a, b, dot);
    }
    #pragma unroll
    for (int o = 16; o > 0; o >>= 1) dot += __shfl_xor_sync(0xffffffffu, dot, o);
    if (lane == 0) g_norm[e] = dot / __ldg(normc + __ldg(et + e));
}

// ---------------- pass B: CSR accumulate into S (smem) --------------------
#define WSLOT (KREL + 16)
#define E1_SMEM (8 * WSLOT * 4)

__global__ __launch_bounds__(256) void edge1_acc_kernel(
    const int* __restrict__ ei, const int* __restrict__ et)
{
    extern __shared__ float sm[];
    int t = threadIdx.x, w = t >> 5, lane = t & 31;
    int dst = blockIdx.x * 8 + w;
    float* sW = sm + w * WSLOT;

    for (int i = t; i < 8 * WSLOT; i += 256) sm[i] = 0.f;
    __syncthreads();

    int e0 = g_rowptr[dst], e1 = g_rowptr[dst + 1];
    int srcN = 0, rN = 0;
    float nrmN = 0.f;
    if (e0 < e1) {
        int eid = g_eids[e0];
        srcN = __ldg(ei + eid);
        rN   = __ldg(et + eid);
        nrmN = g_norm[eid];
    }
    for (int j = e0; j < e1; j++) {
        int src = srcN, r = rN;
        float nrm = nrmN;
        if (j + 1 < e1) {
            int eid = g_eids[j + 1];
            srcN = __ldg(ei + eid);
            rN   = __ldg(et + eid);
            nrmN = g_norm[eid];
        }
        const __half* ps = g_xh + (size_t)src * DIN;
        float* sr = sW + r * DIN;
        #pragma unroll
        for (int i = 0; i < 12; i++)
            sr[lane + 32 * i] += nrm * __half2float(__ldg(ps + lane + 32 * i));
        if (lane == 0) sW[KREL + r] += nrm;
    }
    __syncwarp();

    size_t ob = (size_t)dst * KREL;
    #pragma unroll
    for (int i = 0; i < KREL / 64; i++) {
        int idx = i * 64 + lane * 2;
        *reinterpret_cast<__half2*>(g_Shi + ob + idx) =
            __floats2half2_rn(sW[idx], sW[idx + 1]);
    }
    if (lane < Rr) g_C[dst * Rr + lane] = sW[KREL + lane];
}

// ---------------- HMMA GEMM (single-term fp16) -----------------------------
// CTA tile 128x256, 8 warps (2x4), warp tile 64x64, K-chunk 64, 3-stage, 1 sync/iter.
#define STAGE_SZ 49152
#define SM_BIAS  (3 * STAGE_SZ)              // 147456
#define SMEM_DYN (SM_BIAS + Rr * 256 * 4)    // 156672

template<int MODE>
__global__ __launch_bounds__(256, 1) void mma_gemm_kernel(
    const float* __restrict__ relb,
    const float* __restrict__ mplb,
    const float* __restrict__ mpsb)
{
    constexpr int KTOT = (MODE == 1) ? KREL : DH;
    constexpr int ITERS = KTOT / 64;
    const __half* Amat = (MODE == 1) ? g_Shi : g_x1;
    const __half* Bmat = (MODE == 1) ? g_Brel : g_Bmp;

    extern __shared__ char smem[];
    uint32_t sb = smem_u32(smem);
    const int t = threadIdx.x, wid = t >> 5, lid = t & 31;
    const int bm = blockIdx.x * 128, bn = blockIdx.y * 256;
    const int wr = wid >> 2, wc = wid & 3;
    const int wm = wr * 64, wn = wc * 64;

    float* biasS = reinterpret_cast<float*>(smem + SM_BIAS);
    if (MODE == 1) {
        for (int i = t; i < Rr * 256; i += 256)
            biasS[i] = relb[(i >> 8) * DH + bn + (i & 255)];
    } else {
        if (t < 256) biasS[t] = (bn < DH) ? mplb[bn + t] : mpsb[bn - DH + t];
    }
    __syncthreads();

    auto issue_copy = [&](int s, int kc) {
        uint32_t stb = sb + s * STAGE_SZ;
        #pragma unroll
        for (int q = 0; q < 12; q++) {
            int id = t + q * 256;
            const __half* p;
            int rb;
            uint32_t tbase;
            int i2;
            if (q < 4) { i2 = id;        p = Amat; rb = bm; tbase = 0; }
            else       { i2 = id - 1024; p = Bmat; rb = bn; tbase = 16384; }
            int row = i2 >> 3, ch = i2 & 7;
            const __half* gp = p + (size_t)(rb + row) * KTOT + kc + ch * 8;
            uint32_t sa = stb + tbase + row * 128 + 16 * (ch ^ (row & 7));
            CP_ASYNC16(sa, gp);
        }
    };

    issue_copy(0, 0); CP_COMMIT();
    issue_copy(1, 64); CP_COMMIT();

    float acc[4][8][4];
    #pragma unroll
    for (int a = 0; a < 4; a++)
        #pragma unroll
        for (int b = 0; b < 8; b++)
            #pragma unroll
            for (int c = 0; c < 4; c++) acc[a][b][c] = 0.f;

    const int arow = wm + (lid & 15);
    const int acsel = (lid >> 4);
    const int axor = arow & 7;
    const int brow = wn + (lid & 7) + ((lid >> 4) << 3);
    const int bcsel = (lid >> 3) & 1;
    const int bxor = lid & 7;

    for (int it = 0; it < ITERS; it++) {
        if (it == ITERS - 1) CP_WAIT0(); else CP_WAIT1();
        __syncthreads();
        if (it + 2 < ITERS) { issue_copy((it + 2) % 3, (it + 2) * 64); CP_COMMIT(); }

        uint32_t stb = sb + (it % 3) * STAGE_SZ;
        uint32_t aA = stb, aB = stb + 16384;

        #pragma unroll
        for (int kk = 0; kk < 4; kk++) {
            uint32_t ar[4][4];
            #pragma unroll
            for (int mi = 0; mi < 4; mi++) {
                uint32_t off = (uint32_t)((arow + mi * 16) * 128
                             + 16 * ((kk * 2 + acsel) ^ axor));
                LDMX4(ar[mi], aA + off);
            }
            uint32_t br[4][4];
            #pragma unroll
            for (int pr = 0; pr < 4; pr++) {
                uint32_t off = (uint32_t)((brow + pr * 16) * 128
                             + 16 * ((kk * 2 + bcsel) ^ bxor));
                LDMX4(br[pr], aB + off);
            }
            #pragma unroll
            for (int mi = 0; mi < 4; mi++) {
                #pragma unroll
                for (int ni = 0; ni < 8; ni++) {
                    int pr = ni >> 1, hf = ni & 1;
                    MMAF16(acc[mi][ni], ar[mi], br[pr][hf * 2], br[pr][hf * 2 + 1]);
                }
            }
        }
    }
    __syncthreads();

    // ---------------- epilogue ----------------
    const int g = lid >> 2, tq = lid & 3;
    if (MODE == 1) {
        #pragma unroll
        for (int mi = 0; mi < 4; mi++) {
            #pragma unroll
            for (int h = 0; h < 2; h++) {
                int row = bm + wm + mi * 16 + g + h * 8;
                float cv[Rr];
                #pragma unroll
                for (int r = 0; r < Rr; r++) cv[r] = g_C[(size_t)row * Rr + r];
                #pragma unroll
                for (int ni = 0; ni < 8; ni++) {
                    int cl = wn + ni * 8 + tq * 2;
                    float v0 = acc[mi][ni][h * 2 + 0];
                    float v1 = acc[mi][ni][h * 2 + 1];
                    #pragma unroll
                    for (int r = 0; r < Rr; r++) {
                        v0 += cv[r] * biasS[r * 256 + cl];
                        v1 += cv[r] * biasS[r * 256 + cl + 1];
                    }
                    v0 = v0 > 0.f ? v0 : 0.f;
                    v1 = v1 > 0.f ? v1 : 0.f;
                    *reinterpret_cast<__half2*>(g_x1 + (size_t)row * DH + bn + cl) =
                        __floats2half2_rn(v0, v1);
                }
            }
        }
    } else {
        __half* dst = (bn < DH) ? g_hm : g_self;
        int bnl = (bn < DH) ? bn : bn - DH;
        #pragma unroll
        for (int mi = 0; mi < 4; mi++) {
            #pragma unroll
            for (int h = 0; h < 2; h++) {
                int row = bm + wm + mi * 16 + g + h * 8;
                #pragma unroll
                for (int ni = 0; ni < 8; ni++) {
                    int cl = wn + ni * 8 + tq * 2;
                    float v0 = acc[mi][ni][h * 2 + 0] + biasS[cl];
                    float v1 = acc[mi][ni][h * 2 + 1] + biasS[cl + 1];
                    *reinterpret_cast<__half2*>(dst + (size_t)row * DH + bnl + cl) =
                        __floats2half2_rn(v0, v1);
                }
            }
        }
    }
}

// ---------------- phase 4+5 fused: CSR gather + relu + colsum -------------
__global__ __launch_bounds__(256) void scatter2_csr_kernel(const int* __restrict__ ei)
{
    __shared__ float colsum[DH];
    int t = threadIdx.x, w = t >> 5, lane = t & 31;
    int dst = blockIdx.x * 8 + w;
    for (int i = t; i < DH; i += 256) colsum[i] = 0.f;
    __syncthreads();

    float acc[24];
    #pragma unroll
    for (int i = 0; i < 24; i++) acc[i] = 0.f;

    int e0 = g_rowptr[dst], e1 = g_rowptr[dst + 1];
    int srcN = 0;
    if (e0 < e1) srcN = __ldg(ei + g_eids[e0]);
    for (int j = e0; j < e1; j++) {
        int src = srcN;
        if (j + 1 < e1) srcN = __ldg(ei + g_eids[j + 1]);
        const uint4* hr = reinterpret_cast<const uint4*>(g_hm + (size_t)src * DH);
        #pragma unroll
        for (int i = 0; i < 3; i++) {
            uint4 v = hr[lane + 32 * i];
            uint32_t wds[4] = {v.x, v.y, v.z, v.w};
            #pragma unroll
            for (int q = 0; q < 4; q++) {
                float2 f = __half22float2(*reinterpret_cast<__half2*>(&wds[q]));
                acc[i * 8 + q * 2 + 0] += f.x;
                acc[i * 8 + q * 2 + 1] += f.y;
            }
        }
    }
    const uint4* sr = reinterpret_cast<const uint4*>(g_self + (size_t)dst * DH);
    #pragma unroll
    for (int i = 0; i < 3; i++) {
        uint4 v = sr[lane + 32 * i];
        uint32_t wds[4] = {v.x, v.y, v.z, v.w};
        #pragma unroll
        for (int q = 0; q < 4; q++) {
            float2 f = __half22float2(*reinterpret_cast<__half2*>(&wds[q]));
            int h = (lane + 32 * i) * 8 + q * 2;
            float x0 = acc[i * 8 + q * 2 + 0] + f.x;
            float x1 = acc[i * 8 + q * 2 + 1] + f.y;
            x0 = x0 > 0.f ? x0 : 0.f;
            x1 = x1 > 0.f ? x1 : 0.f;
            atomicAdd(&colsum[h + 0], x0);
            atomicAdd(&colsum[h + 1], x1);
        }
    }
    __syncthreads();
    if (t < DH / 4) {
        float4 v = reinterpret_cast<float4*>(colsum)[t];
        atomicAdd(reinterpret_cast<float4*>(g_pooled) + t, v);
    }
}

// ---------------- phase 6: readout ----------------------------------------
__global__ void readout_kernel(const float* __restrict__ oW,
                               const float* __restrict__ ob,
                               float* __restrict__ out)
{
    __shared__ float sred[NC][256];
    int t = threadIdx.x;
    float p[NC] = {0.f, 0.f, 0.f, 0.f, 0.f};
    for (int h = t; h < DH; h += 256) {
        float pv = g_pooled[h] * (1.0f / Nn);
        #pragma unroll
        for (int c = 0; c < NC; c++) p[c] += pv * oW[c * DH + h];
    }
    #pragma unroll
    for (int c = 0; c < NC; c++) sred[c][t] = p[c];
    __syncthreads();
    for (int s = 128; s > 0; s >>= 1) {
        if (t < s) {
            #pragma unroll
            for (int c = 0; c < NC; c++) sred[c][t] += sred[c][t + s];
        }
        __syncthreads();
    }
    if (t < NC) out[t] = sred[t][0] + ob[t];
}

// ---------------- launch ---------------------------------------------------
extern "C" void kernel_launch(void* const* d_in, const int* in_sizes, int n_in,
                              void* d_out, int out_size)
{
    const float* x     = (const float*)d_in[0];
    const int*   ei    = (const int*)d_in[1];
    const int*   et    = (const int*)d_in[2];
    const float* relW  = (const float*)d_in[3];
    const float* relb  = (const float*)d_in[4];
    const float* normc = (const float*)d_in[5];
    const float* mplW  = (const float*)d_in[6];
    const float* mplb  = (const float*)d_in[7];
    const float* mpsW  = (const float*)d_in[8];
    const float* mpsb  = (const float*)d_in[9];
    const float* oW    = (const float*)d_in[10];
    const float* ob    = (const float*)d_in[11];
    float* out = (float*)d_out;

    cudaFuncSetAttribute(edge1_acc_kernel, cudaFuncAttributeMaxDynamicSharedMemorySize, E1_SMEM);
    cudaFuncSetAttribute(mma_gemm_kernel<1>, cudaFuncAttributeMaxDynamicSharedMemorySize, SMEM_DYN);
    cudaFuncSetAttribute(mma_gemm_kernel<2>, cudaFuncAttributeMaxDynamicSharedMemorySize, SMEM_DYN);

    zero_small_kernel<<<(Nn + 255) / 256, 256>>>();
    csr_count_kernel<<<Ee / 256, 256>>>(ei);
    csr_scan_kernel<<<1, 256>>>();
    csr_fill_kernel<<<Ee / 256, 256>>>(ei);

    conv_x_kernel<<<(Nn * DIN / 4 + 255) / 256, 256>>>(x);
    wconv_rel_kernel<<<(Rr * DH * DIN + 255) / 256, 256>>>(relW);
    wconv_mp_kernel<<<(NMP * DH + 255) / 256, 256>>>(mplW, mpsW);

    norm_kernel<<<Ee / 8, 256>>>(ei, et, normc);
    edge1_acc_kernel<<<Nn / 8, 256, E1_SMEM>>>(ei, et);

    dim3 g1(Nn / 128, DH / 256);       // 128 x 3
    mma_gemm_kernel<1><<<g1, 256, SMEM_DYN>>>(relb, mplb, mpsb);
    dim3 g2(Nn / 128, NMP / 256);      // 128 x 6
    mma_gemm_kernel<2><<<g2, 256, SMEM_DYN>>>(relb, mplb, mpsb);

    scatter2_csr_kernel<<<Nn / 8, 256>>>(ei);
    readout_kernel<<<1, 256>>>(oW, ob, out);
}

// round 16
// speedup vs baseline: 1.0740x; 1.0740x over previous
#include <cuda_runtime.h>
#include <cuda_fp16.h>
#include <cstdint>

#define Nn 16384
#define Ee 262144
#define Rr 9
#define DIN 384
#define DH 768
#define NC 5
#define KREL (Rr * DIN)     // 3456
#define NMP (2 * DH)        // 1536

// ---------------- scratch (device globals) --------------------------------
__device__ __align__(256) __half g_xh[(size_t)Nn * DIN];
__device__ __align__(256) __half g_Shi[(size_t)Nn * KREL];
__device__ __align__(256) float g_C[Nn * Rr];
__device__ __align__(256) __half g_Brel[(size_t)DH * KREL];
__device__ __align__(256) __half g_x1[(size_t)Nn * DH];
__device__ __align__(256) __half g_Bmp[(size_t)NMP * DH];
__device__ __align__(256) __half g_hm[(size_t)Nn * DH];
__device__ __align__(256) __half g_self[(size_t)Nn * DH];
__device__ float g_pooled[DH];          // zeroed at module load; readout re-zeroes
// CSR
__device__ int g_cnt[Nn];               // zeroed at module load; csr_scan re-zeroes
__device__ int g_rowptr[Nn + 1];
__device__ int g_woff[Nn];
__device__ int g_eids[Ee];

// ---------------- PTX helpers ---------------------------------------------
__device__ __forceinline__ uint32_t smem_u32(const void* p) {
    uint32_t a;
    asm("{ .reg .u64 t; cvta.to.shared.u64 t, %1; cvt.u32.u64 %0, t; }" : "=r"(a) : "l"(p));
    return a;
}

#define CP_ASYNC16(sa, gp) \
    asm volatile("cp.async.cg.shared.global [%0], [%1], 16;" :: "r"(sa), "l"(gp))
#define CP_COMMIT() asm volatile("cp.async.commit_group;" ::: "memory")
#define CP_WAIT2()  asm volatile("cp.async.wait_group 2;" ::: "memory")

#define LDMX4(r, a) \
    asm volatile("ldmatrix.sync.aligned.m8n8.x4.shared.b16 {%0,%1,%2,%3}, [%4];" \
        : "=r"((r)[0]), "=r"((r)[1]), "=r"((r)[2]), "=r"((r)[3]) : "r"(a))

#define MMAF16(c, a, b0, b1) \
    asm volatile("mma.sync.aligned.m16n8k16.row.col.f32.f16.f16.f32 " \
        "{%0,%1,%2,%3}, {%4,%5,%6,%7}, {%8,%9}, {%0,%1,%2,%3};" \
        : "+f"((c)[0]), "+f"((c)[1]), "+f"((c)[2]), "+f"((c)[3]) \
        : "r"((a)[0]), "r"((a)[1]), "r"((a)[2]), "r"((a)[3]), "r"(b0), "r"(b1))

// ---------------- CSR build ------------------------------------------------
__global__ void csr_count_kernel(const int* __restrict__ ei) {
    int e = blockIdx.x * blockDim.x + threadIdx.x;
    if (e < Ee) atomicAdd(&g_cnt[__ldg(ei + Ee + e)], 1);
}

__global__ void csr_scan_kernel() {
    __shared__ int ssum[256];
    int t = threadIdx.x;
    int base = t * 64;
    int s = 0;
    for (int i = 0; i < 64; i++) s += g_cnt[base + i];
    ssum[t] = s;
    __syncthreads();
    for (int off = 1; off < 256; off <<= 1) {
        int u = (t >= off) ? ssum[t - off] : 0;
        __syncthreads();
        ssum[t] += u;
        __syncthreads();
    }
    int run = (t == 0) ? 0 : ssum[t - 1];
    for (int i = 0; i < 64; i++) {
        int c = g_cnt[base + i];
        g_cnt[base + i] = 0;            // restore zero for next call
        g_rowptr[base + i] = run;
        g_woff[base + i] = run;
        run += c;
    }
    if (t == 255) g_rowptr[Nn] = run;
}

__global__ void csr_fill_kernel(const int* __restrict__ ei) {
    int e = blockIdx.x * blockDim.x + threadIdx.x;
    if (e >= Ee) return;
    int pos = atomicAdd(&g_woff[__ldg(ei + Ee + e)], 1);
    g_eids[pos] = e;
}

// ---------------- converts -------------------------------------------------
__global__ void conv_x_kernel(const float* __restrict__ x) {
    int i = blockIdx.x * blockDim.x + threadIdx.x;     // handles 4 floats
    if (i >= Nn * DIN / 4) return;
    float4 v = reinterpret_cast<const float4*>(x)[i];
    reinterpret_cast<__half2*>(g_xh)[2 * i]     = __floats2half2_rn(v.x, v.y);
    reinterpret_cast<__half2*>(g_xh)[2 * i + 1] = __floats2half2_rn(v.z, v.w);
}

__global__ void wconv_rel_kernel(const float* __restrict__ relW) {
    int idx = blockIdx.x * blockDim.x + threadIdx.x;
    if (idx >= Rr * DH * DIN) return;
    int k = idx % DIN;
    int h = (idx / DIN) % DH;
    int r = idx / (DIN * DH);
    g_Brel[(size_t)h * KREL + r * DIN + k] = __float2half_rn(relW[idx]);
}

__global__ void wconv_mp_kernel(const float* __restrict__ mplW, const float* __restrict__ mpsW) {
    int idx = blockIdx.x * blockDim.x + threadIdx.x;
    if (idx >= NMP * DH) return;
    int k = idx % DH;
    int n = idx / DH;
    float v = (n < DH) ? mplW[(size_t)n * DH + k] : mpsW[(size_t)(n - DH) * DH + k];
    g_Bmp[idx] = __float2half_rn(v);
}

// ---------------- phase 1: fused CSR gather edge aggregation (fp16 x) -----
#define WSLOT (KREL + 16)
#define E1_SMEM (8 * WSLOT * 4)

__global__ __launch_bounds__(256) void edge1_csr_kernel(
    const int* __restrict__ ei, const int* __restrict__ et,
    const float* __restrict__ normc)
{
    extern __shared__ float sm[];
    int t = threadIdx.x, w = t >> 5, lane = t & 31;
    int dst = blockIdx.x * 8 + w;
    float* sW = sm + w * WSLOT;

    float4* z4 = reinterpret_cast<float4*>(sm);
    float4 zz = make_float4(0.f, 0.f, 0.f, 0.f);
    for (int i = t; i < 8 * WSLOT / 4; i += 256) z4[i] = zz;
    __syncthreads();

    // preload x[dst] (fp16 -> fp32 regs)
    const __half2* pd = reinterpret_cast<const __half2*>(g_xh + (size_t)dst * DIN);
    float xd[12];
    #pragma unroll
    for (int i = 0; i < 6; i++) {
        float2 f = __half22float2(__ldg(pd + lane + 32 * i));
        xd[2 * i] = f.x; xd[2 * i + 1] = f.y;
    }

    int e0 = g_rowptr[dst], e1 = g_rowptr[dst + 1];
    int srcN = 0, rN = 0;
    if (e0 < e1) {
        int eid = g_eids[e0];
        srcN = __ldg(ei + eid);
        rN   = __ldg(et + eid);
    }
    for (int j = e0; j < e1; j++) {
        int src = srcN, r = rN;
        if (j + 1 < e1) {
            int eid = g_eids[j + 1];
            srcN = __ldg(ei + eid);
            rN   = __ldg(et + eid);
        }
        const __half2* ps = reinterpret_cast<const __half2*>(g_xh + (size_t)src * DIN);
        __half2 hv[6];
        #pragma unroll
        for (int i = 0; i < 6; i++) hv[i] = __ldg(ps + lane + 32 * i);

        float d0 = 0.f, d1 = 0.f;
        float xf[12];
        #pragma unroll
        for (int i = 0; i < 6; i++) {
            float2 f = __half22float2(hv[i]);
            xf[2 * i] = f.x; xf[2 * i + 1] = f.y;
            d0 = fmaf(f.x, xd[2 * i], d0);
            d1 = fmaf(f.y, xd[2 * i + 1], d1);
        }
        float dot = d0 + d1;
        #pragma unroll
        for (int o = 16; o > 0; o >>= 1) dot += __shfl_xor_sync(0xffffffffu, dot, o);
        float nrm = dot / __ldg(normc + r);

        float2* sr2 = reinterpret_cast<float2*>(sW + r * DIN);
        #pragma unroll
        for (int i = 0; i < 6; i++) {
            float2 cur = sr2[lane + 32 * i];
            cur.x = fmaf(nrm, xf[2 * i], cur.x);
            cur.y = fmaf(nrm, xf[2 * i + 1], cur.y);
            sr2[lane + 32 * i] = cur;
        }
        if (lane == 0) sW[KREL + r] += nrm;
    }
    __syncwarp();

    size_t ob = (size_t)dst * KREL;
    #pragma unroll
    for (int i = 0; i < KREL / 64; i++) {
        int idx = i * 64 + lane * 2;
        *reinterpret_cast<__half2*>(g_Shi + ob + idx) =
            __floats2half2_rn(sW[idx], sW[idx + 1]);
    }
    if (lane < Rr) g_C[dst * Rr + lane] = sW[KREL + lane];
}

// ---------------- HMMA GEMM (single-term fp16, R8 loop) --------------------
#define STAGE_SZ 49152
#define SM_BIAS  (3 * STAGE_SZ)              // 147456
#define SMEM_DYN (SM_BIAS + Rr * 256 * 4)    // 156672

template<int MODE>
__global__ __launch_bounds__(256, 1) void mma_gemm_kernel(
    const float* __restrict__ relb,
    const float* __restrict__ mplb,
    const float* __restrict__ mpsb)
{
    constexpr int KTOT = (MODE == 1) ? KREL : DH;
    constexpr int ITERS = KTOT / 64;
    const __half* Amat = (MODE == 1) ? g_Shi : g_x1;
    const __half* Bmat = (MODE == 1) ? g_Brel : g_Bmp;

    extern __shared__ char smem[];
    uint32_t sb = smem_u32(smem);
    const int t = threadIdx.x, wid = t >> 5, lid = t & 31;
    const int bm = blockIdx.x * 128, bn = blockIdx.y * 256;
    const int wr = wid >> 2, wc = wid & 3;
    const int wm = wr * 64, wn = wc * 64;

    float* biasS = reinterpret_cast<float*>(smem + SM_BIAS);
    if (MODE == 1) {
        for (int i = t; i < Rr * 256; i += 256)
            biasS[i] = relb[(i >> 8) * DH + bn + (i & 255)];
    } else {
        if (t < 256) biasS[t] = (bn < DH) ? mplb[bn + t] : mpsb[bn - DH + t];
    }
    __syncthreads();

    auto issue_copy = [&](int s, int kc) {
        uint32_t stb = sb + s * STAGE_SZ;
        #pragma unroll
        for (int q = 0; q < 12; q++) {
            int id = t + q * 256;
            const __half* p;
            int rb;
            uint32_t tbase;
            int i2;
            if (q < 4) { i2 = id;        p = Amat; rb = bm; tbase = 0; }
            else       { i2 = id - 1024; p = Bmat; rb = bn; tbase = 16384; }
            int row = i2 >> 3, ch = i2 & 7;
            const __half* gp = p + (size_t)(rb + row) * KTOT + kc + ch * 8;
            uint32_t sa = stb + tbase + row * 128 + 16 * (ch ^ (row & 7));
            CP_ASYNC16(sa, gp);
        }
    };

    issue_copy(0, 0); CP_COMMIT();
    issue_copy(1, 64); CP_COMMIT();

    float acc[4][8][4];
    #pragma unroll
    for (int a = 0; a < 4; a++)
        #pragma unroll
        for (int b = 0; b < 8; b++)
            #pragma unroll
            for (int c = 0; c < 4; c++) acc[a][b][c] = 0.f;

    const int arow = wm + (lid & 15);
    const int acsel = (lid >> 4);
    const int axor = arow & 7;
    const int brow = wn + (lid & 7) + ((lid >> 4) << 3);
    const int bcsel = (lid >> 3) & 1;
    const int bxor = lid & 7;

    for (int it = 0; it < ITERS; it++) {
        if (it + 2 < ITERS) issue_copy((it + 2) % 3, (it + 2) * 64);
        CP_COMMIT();
        CP_WAIT2();
        __syncthreads();

        uint32_t stb = sb + (it % 3) * STAGE_SZ;
        uint32_t aA = stb, aB = stb + 16384;

        #pragma unroll
        for (int kk = 0; kk < 4; kk++) {
            uint32_t ar[4][4];
            #pragma unroll
            for (int mi = 0; mi < 4; mi++) {
                uint32_t off = (uint32_t)((arow + mi * 16) * 128
                             + 16 * ((kk * 2 + acsel) ^ axor));
                LDMX4(ar[mi], aA + off);
            }
            uint32_t br[4][4];
            #pragma unroll
            for (int pr = 0; pr < 4; pr++) {
                uint32_t off = (uint32_t)((brow + pr * 16) * 128
                             + 16 * ((kk * 2 + bcsel) ^ bxor));
                LDMX4(br[pr], aB + off);
            }
            #pragma unroll
            for (int mi = 0; mi < 4; mi++) {
                #pragma unroll
                for (int ni = 0; ni < 8; ni++) {
                    int pr = ni >> 1, hf = ni & 1;
                    MMAF16(acc[mi][ni], ar[mi], br[pr][hf * 2], br[pr][hf * 2 + 1]);
                }
            }
        }
        __syncthreads();
    }

    // ---------------- epilogue ----------------
    const int g = lid >> 2, tq = lid & 3;
    if (MODE == 1) {
        #pragma unroll
        for (int mi = 0; mi < 4; mi++) {
            #pragma unroll
            for (int h = 0; h < 2; h++) {
                int row = bm + wm + mi * 16 + g + h * 8;
                float cv[Rr];
                #pragma unroll
                for (int r = 0; r < Rr; r++) cv[r] = g_C[(size_t)row * Rr + r];
                #pragma unroll
                for (int ni = 0; ni < 8; ni++) {
                    int cl = wn + ni * 8 + tq * 2;
                    float v0 = acc[mi][ni][h * 2 + 0];
                    float v1 = acc[mi][ni][h * 2 + 1];
                    #pragma unroll
                    for (int r = 0; r < Rr; r++) {
                        v0 += cv[r] * biasS[r * 256 + cl];
                        v1 += cv[r] * biasS[r * 256 + cl + 1];
                    }
                    v0 = v0 > 0.f ? v0 : 0.f;
                    v1 = v1 > 0.f ? v1 : 0.f;
                    *reinterpret_cast<__half2*>(g_x1 + (size_t)row * DH + bn + cl) =
                        __floats2half2_rn(v0, v1);
                }
            }
        }
    } else {
        __half* dst = (bn < DH) ? g_hm : g_self;
        int bnl = (bn < DH) ? bn : bn - DH;
        #pragma unroll
        for (int mi = 0; mi < 4; mi++) {
            #pragma unroll
            for (int h = 0; h < 2; h++) {
                int row = bm + wm + mi * 16 + g + h * 8;
                #pragma unroll
                for (int ni = 0; ni < 8; ni++) {
                    int cl = wn + ni * 8 + tq * 2;
                    float v0 = acc[mi][ni][h * 2 + 0] + biasS[cl];
                    float v1 = acc[mi][ni][h * 2 + 1] + biasS[cl + 1];
                    *reinterpret_cast<__half2*>(dst + (size_t)row * DH + bnl + cl) =
                        __floats2half2_rn(v0, v1);
                }
            }
        }
    }
}

// ---------------- phase 4+5 fused: CSR gather + relu + colsum -------------
__global__ __launch_bounds__(256) void scatter2_csr_kernel(const int* __restrict__ ei)
{
    __shared__ float colsum[DH];
    int t = threadIdx.x, w = t >> 5, lane = t & 31;
    int dst = blockIdx.x * 8 + w;
    for (int i = t; i < DH; i += 256) colsum[i] = 0.f;
    __syncthreads();

    float acc[24];
    #pragma unroll
    for (int i = 0; i < 24; i++) acc[i] = 0.f;

    int e0 = g_rowptr[dst], e1 = g_rowptr[dst + 1];
    int srcN = 0;
    if (e0 < e1) srcN = __ldg(ei + g_eids[e0]);
    for (int j = e0; j < e1; j++) {
        int src = srcN;
        if (j + 1 < e1) srcN = __ldg(ei + g_eids[j + 1]);
        const uint4* hr = reinterpret_cast<const uint4*>(g_hm + (size_t)src * DH);
        #pragma unroll
        for (int i = 0; i < 3; i++) {
            uint4 v = hr[lane + 32 * i];
            uint32_t wds[4] = {v.x, v.y, v.z, v.w};
            #pragma unroll
            for (int q = 0; q < 4; q++) {
                float2 f = __half22float2(*reinterpret_cast<__half2*>(&wds[q]));
                acc[i * 8 + q * 2 + 0] += f.x;
                acc[i * 8 + q * 2 + 1] += f.y;
            }
        }
    }
    const uint4* sr = reinterpret_cast<const uint4*>(g_self + (size_t)dst * DH);
    #pragma unroll
    for (int i = 0; i < 3; i++) {
        uint4 v = sr[lane + 32 * i];
        uint32_t wds[4] = {v.x, v.y, v.z, v.w};
        #pragma unroll
        for (int q = 0; q < 4; q++) {
            float2 f = __half22float2(*reinterpret_cast<__half2*>(&wds[q]));
            int h = (lane + 32 * i) * 8 + q * 2;
            float x0 = acc[i * 8 + q * 2 + 0] + f.x;
            float x1 = acc[i * 8 + q * 2 + 1] + f.y;
            x0 = x0 > 0.f ? x0 : 0.f;
            x1 = x1 > 0.f ? x1 : 0.f;
            atomicAdd(&colsum[h + 0], x0);
            atomicAdd(&colsum[h + 1], x1);
        }
    }
    __syncthreads();
    if (t < DH / 4) {
        float4 v = reinterpret_cast<float4*>(colsum)[t];
        atomicAdd(reinterpret_cast<float4*>(g_pooled) + t, v);
    }
}

// ---------------- phase 6: readout (self-zeroes g_pooled) ------------------
__global__ void readout_kernel(const float* __restrict__ oW,
                               const float* __restrict__ ob,
                               float* __restrict__ out)
{
    __shared__ float sred[NC][256];
    int t = threadIdx.x;
    float p[NC] = {0.f, 0.f, 0.f, 0.f, 0.f};
    for (int h = t; h < DH; h += 256) {
        float pv = g_pooled[h] * (1.0f / Nn);
        g_pooled[h] = 0.f;              // restore zero for next call
        #pragma unroll
        for (int c = 0; c < NC; c++) p[c] += pv * oW[c * DH + h];
    }
    #pragma unroll
    for (int c = 0; c < NC; c++) sred[c][t] = p[c];
    __syncthreads();
    for (int s = 128; s > 0; s >>= 1) {
        if (t < s) {
            #pragma unroll
            for (int c = 0; c < NC; c++) sred[c][t] += sred[c][t + s];
        }
        __syncthreads();
    }
    if (t < NC) out[t] = sred[t][0] + ob[t];
}

// ---------------- launch ---------------------------------------------------
extern "C" void kernel_launch(void* const* d_in, const int* in_sizes, int n_in,
                              void* d_out, int out_size)
{
    const float* x     = (const float*)d_in[0];
    const int*   ei    = (const int*)d_in[1];
    const int*   et    = (const int*)d_in[2];
    const float* relW  = (const float*)d_in[3];
    const float* relb  = (const float*)d_in[4];
    const float* normc = (const float*)d_in[5];
    const float* mplW  = (const float*)d_in[6];
    const float* mplb  = (const float*)d_in[7];
    const float* mpsW  = (const float*)d_in[8];
    const float* mpsb  = (const float*)d_in[9];
    const float* oW    = (const float*)d_in[10];
    const float* ob    = (const float*)d_in[11];
    float* out = (float*)d_out;

    cudaFuncSetAttribute(edge1_csr_kernel, cudaFuncAttributeMaxDynamicSharedMemorySize, E1_SMEM);
    cudaFuncSetAttribute(mma_gemm_kernel<1>, cudaFuncAttributeMaxDynamicSharedMemorySize, SMEM_DYN);
    cudaFuncSetAttribute(mma_gemm_kernel<2>, cudaFuncAttributeMaxDynamicSharedMemorySize, SMEM_DYN);

    conv_x_kernel<<<(Nn * DIN / 4 + 255) / 256, 256>>>(x);
    csr_count_kernel<<<Ee / 256, 256>>>(ei);
    csr_scan_kernel<<<1, 256>>>();
    csr_fill_kernel<<<Ee / 256, 256>>>(ei);

    wconv_rel_kernel<<<(Rr * DH * DIN + 255) / 256, 256>>>(relW);
    wconv_mp_kernel<<<(NMP * DH + 255) / 256, 256>>>(mplW, mpsW);

    edge1_csr_kernel<<<Nn / 8, 256, E1_SMEM>>>(ei, et, normc);

    dim3 g1(Nn / 128, DH / 256);       // 128 x 3
    mma_gemm_kernel<1><<<g1, 256, SMEM_DYN>>>(relb, mplb, mpsb);
    dim3 g2(Nn / 128, NMP / 256);      // 128 x 6
    mma_gemm_kernel<2><<<g2, 256, SMEM_DYN>>>(relb, mplb, mpsb);

    scatter2_csr_kernel<<<Nn / 8, 256>>>(ei);
    readout_kernel<<<1, 256>>>(oW, ob, out);
}